// round 13
// baseline (speedup 1.0000x reference)
#include <cuda_runtime.h>
#include <cstdint>
#include <cstddef>

#define TSTEPS 1024
#define BATCH  128
#define DIN    64
#define HH     512
#define NGRP   16        // row groups (8 rows each)
#define NC     16        // CTAs per cluster (32-col slices)
#define RG     8         // rows per group
#define CW     32        // cols per CTA slice
#define NTHR   256
#define NW     8         // warps = k-phases
#define HP     10        // float pitch per k-row (8 rows + 2 pad)
#define EPSF   1e-5f

// ---- shared memory layout (float offsets) ----
#define OF_H0X   0                         // [576][HP]: rows 0..63 = x_t, 64..575 = h0n
#define OF_H1X   (OF_H0X + 576 * HP)       // [512][HP]
#define OF_RED   (OF_H1X + 512 * HP)       // [8][32][10]
#define OF_INBOX (OF_RED + 8 * 32 * 10)    // [2][RG][HH]
#define OF_PART  (OF_INBOX + 2 * RG * HH)  // [2][NC][RG] float2
#define OF_SG0   (OF_PART + 2 * NC * RG * 2)
#define OF_SB0   (OF_SG0 + HH)
#define OF_SG1   (OF_SB0 + HH)
#define OF_SB1   (OF_SG1 + HH)
#define OF_CB0   (OF_SB1 + HH)
#define OF_CB1   (OF_CB0 + CW)
#define OF_SP    (OF_CB1 + CW)             // [8] float2 (per-warp LN partials)
#define OF_SMU   (OF_SP + 16)
#define OF_SRS   (OF_SMU + RG)
#define SMEM_FL  (OF_SRS + RG)
#define SMEM_BYTES (SMEM_FL * 4)

typedef unsigned long long ull;

__device__ __forceinline__ ull ffma2(ull a, ull b, ull c) {
    ull d;
    asm("fma.rn.f32x2 %0, %1, %2, %3;" : "=l"(d) : "l"(a), "l"(b), "l"(c));
    return d;
}
__device__ __forceinline__ ull dup2(float f) {
    ull d;
    asm("mov.b64 %0, {%1, %1};" : "=l"(d) : "f"(f));
    return d;
}
__device__ __forceinline__ uint32_t smem_u32(const void* p) {
    uint32_t a;
    asm("{ .reg .u64 t; cvta.to.shared.u64 t, %1; cvt.u32.u64 %0, t; }" : "=r"(a) : "l"(p));
    return a;
}
__device__ __forceinline__ void st_cluster_v4(uint32_t laddr, int rank, float4 v) {
    uint32_t ra;
    asm volatile("mapa.shared::cluster.u32 %0, %1, %2;" : "=r"(ra) : "r"(laddr), "r"(rank));
    asm volatile("st.shared::cluster.v4.b32 [%0], {%1,%2,%3,%4};"
                 :: "r"(ra), "r"(__float_as_uint(v.x)), "r"(__float_as_uint(v.y)),
                    "r"(__float_as_uint(v.z)), "r"(__float_as_uint(v.w)) : "memory");
}
__device__ __forceinline__ void st_cluster_b64(uint32_t laddr, int rank, ull v) {
    uint32_t ra;
    asm volatile("mapa.shared::cluster.u32 %0, %1, %2;" : "=r"(ra) : "r"(laddr), "r"(rank));
    asm volatile("st.shared::cluster.b64 [%0], %1;" :: "r"(ra), "l"(v) : "memory");
}
__device__ __forceinline__ uint32_t ctarank() {
    uint32_t r;
    asm("mov.u32 %0, %%cluster_ctarank;" : "=r"(r));
    return r;
}
#define CL_ARRIVE() asm volatile("barrier.cluster.arrive.aligned;" ::: "memory")
#define CL_WAIT()   asm volatile("barrier.cluster.wait.aligned;" ::: "memory")

// GEMV slice: ITERS k-steps (k = p + 8*i), 4 cols x 2 rows per thread.
// W from global (L2) — 8 unique lanes x 16B = 128B = 1 wavefront per warp-iter.
template<int ITERS>
__device__ __forceinline__ void gpart(const float* __restrict__ Wp,
                                      const float* __restrict__ hp, ull* acc) {
#pragma unroll 8
    for (int i = 0; i < ITERS; ++i) {
        ulonglong2 w = *(const ulonglong2*)(Wp + (size_t)i * 8 * HH);
        float2 hv = *(const float2*)(hp + i * 8 * HP);
        ull d0 = dup2(hv.x), d1 = dup2(hv.y);
        acc[0] = ffma2(d0, w.x, acc[0]); acc[1] = ffma2(d0, w.y, acc[1]);
        acc[2] = ffma2(d1, w.x, acc[2]); acc[3] = ffma2(d1, w.y, acc[3]);
    }
}

__global__ void __launch_bounds__(NTHR, 2) __cluster_dims__(NC, 1, 1)
rnn_rg8_kernel(
    const float* __restrict__ x,
    const float* __restrict__ Wi0, const float* __restrict__ bi0,
    const float* __restrict__ Wh0, const float* __restrict__ bh0,
    const float* __restrict__ g0,  const float* __restrict__ be0,
    const float* __restrict__ Wi1, const float* __restrict__ bi1,
    const float* __restrict__ Wh1, const float* __restrict__ bh1,
    const float* __restrict__ g1,  const float* __restrict__ be1,
    const float* __restrict__ Wfc, const float* __restrict__ bfc,
    float* __restrict__ out)
{
    extern __shared__ float sm[];
    float*  h0x   = sm + OF_H0X;
    float*  h1x   = sm + OF_H1X;
    float*  red   = sm + OF_RED;
    float*  inbox = sm + OF_INBOX;
    float2* part  = (float2*)(sm + OF_PART);
    float*  sg0   = sm + OF_SG0;  float* sb0 = sm + OF_SB0;
    float*  sg1   = sm + OF_SG1;  float* sb1 = sm + OF_SB1;
    float*  cb0   = sm + OF_CB0;  float* cb1 = sm + OF_CB1;
    float2* sp    = (float2*)(sm + OF_SP);
    float*  smu   = sm + OF_SMU;  float* srs = sm + OF_SRS;

    const int tid  = threadIdx.x;
    const int lane = tid & 31;
    const int p    = tid >> 5;          // warp = k-phase (8)
    const int cgo  = (lane & 7) * 4;    // col offset (4-col group, 8 groups = 32 cols)
    const int rqo  = (lane >> 3) * 2;   // row offset (2-row pair, 4 pairs = 8 rows)
    const int rank = (int)ctarank();
    const int g    = blockIdx.x >> 4;
    const int c0   = rank * CW;
    const int row0 = g * RG;

    const uint32_t inbox_b = smem_u32(inbox);
    const uint32_t part_b  = smem_u32(part);

    // epilogue constants: 1 output/thread; warp == output row
    const int erow = tid >> 5;          // 0..7
    const int ecol = tid & 31;          // 0..31
    const int lane_src = (ecol >> 2) + ((erow >> 1) << 3);
    const int fidx = (((erow & 1) << 1) | ((ecol >> 1) & 1)) * 2 + (ecol & 1);
    const float* rrd = red + lane_src * 10 + fidx;

    // per-thread GEMV base pointers
    const float* wp_i0 = Wi0 + c0 + (size_t)p * HH + cgo;
    const float* wp_h0 = Wh0 + c0 + (size_t)p * HH + cgo;
    const float* wp_i1 = Wi1 + c0 + (size_t)p * HH + cgo;
    const float* wp_h1 = Wh1 + c0 + (size_t)p * HH + cgo;
    const float* hx_x  = h0x + p * HP + rqo;
    const float* hx_h0 = h0x + (64 + p) * HP + rqo;
    const float* hx_h1 = h1x + p * HP + rqo;

    // ---- init ----
    sg0[tid] = g0[tid];             sb0[tid] = be0[tid];
    sg0[tid + 256] = g0[tid + 256]; sb0[tid + 256] = be0[tid + 256];
    sg1[tid] = g1[tid];             sb1[tid] = be1[tid];
    sg1[tid + 256] = g1[tid + 256]; sb1[tid + 256] = be1[tid + 256];
    if (tid < CW) {
        cb0[tid] = bi0[c0 + tid] + bh0[c0 + tid];
        cb1[tid] = bi1[c0 + tid] + bh1[c0 + tid];
    }
    for (int i = tid; i < 576 * HP; i += NTHR) h0x[i] = 0.f;
    for (int i = tid; i < 512 * HP; i += NTHR) h1x[i] = 0.f;
    __syncthreads();
    CL_ARRIVE();     // publishes init; pairs with first E1 wait

    // x staging: 8 rows x 64 k = 512 slots -> 2 per thread
    const int xk = tid & 63, xr0 = tid >> 6;       // rows xr0 and xr0+4
    const float* xbaseA = x + (size_t)(row0 + xr0) * TSTEPS * DIN + xk;
    const float* xbaseB = x + (size_t)(row0 + xr0 + 4) * TSTEPS * DIN + xk;
    float xregA = xbaseA[0], xregB = xbaseB[0];

    ull acc[4];

    for (int t = 0; t < TSTEPS; ++t) {
        h0x[xk * HP + xr0] = xregA;
        h0x[xk * HP + xr0 + 4] = xregB;
        __syncthreads();

        // ---- G0: x·Wi0 + h0n(t-1)·Wh0  (overlaps E1(t-1) exchange) ----
#pragma unroll
        for (int q = 0; q < 4; ++q) acc[q] = 0ull;
        gpart<8>(wp_i0, hx_x, acc);
        gpart<64>(wp_h0, hx_h0, acc);

        CL_WAIT();                       // E1(t-1): inbox[1], part[1] valid
        if (t > 0 && tid < 128) {        // LN stats for h1n(t-1): 8 rows x 16 ranks
            int r = tid >> 4, s16 = tid & 15;
            float2 pv = part[(NC + s16) * RG + r];
#pragma unroll
            for (int o = 8; o; o >>= 1) {
                pv.x += __shfl_xor_sync(0xffffffffu, pv.x, o);
                pv.y += __shfl_xor_sync(0xffffffffu, pv.y, o);
            }
            if (s16 == 0) {
                float mu = pv.x * (1.f / HH);
                float var = pv.y * (1.f / HH) - mu * mu;
                smu[r] = mu; srs[r] = rsqrtf(var + EPSF);
            }
        }
        __syncthreads();
        if (t > 0) {                     // rebuild h1n(t-1): 2 cols/thread
#pragma unroll
            for (int cc = 0; cc < 2; ++cc) {
                int c = tid + cc * 256;
                float gk = sg1[c], bk = sb1[c];
                const float* ib = inbox + RG * HH + c;
                float* hd = h1x + c * HP;
#pragma unroll
                for (int r = 0; r < RG; ++r)
                    hd[r] = (ib[r * HH] - smu[r]) * srs[r] * gk + bk;
            }
        }
        {
            float* rw = red + p * 320 + lane * 10;
#pragma unroll
            for (int q = 0; q < 4; ++q) *(ull*)(rw + 2 * q) = acc[q];
        }
        __syncthreads();

        // ---- epilogue 0 ----
        {
            float z = 0.f;
#pragma unroll
            for (int i = 0; i < NW; ++i) z += rrd[i * 320];
            z += cb0[ecol];
            float cv = tanhf(z) + h0x[(64 + c0 + ecol) * HP + erow];
            inbox[erow * HH + c0 + ecol] = cv;
            float s = cv, q = cv * cv;
#pragma unroll
            for (int o = 16; o; o >>= 1) {
                s += __shfl_xor_sync(0xffffffffu, s, o);
                q += __shfl_xor_sync(0xffffffffu, q, o);
            }
            if (lane == 0) sp[p] = make_float2(s, q);   // warp p == row p
        }
        __syncthreads();
        if (tid < RG) {
            float2 pv = sp[tid];
            part[rank * RG + tid] = pv;
            uint32_t off = (uint32_t)((rank * RG + tid) * 8);
            ull pbv = *(ull*)&pv;
#pragma unroll
            for (int d = 1; d < NC; ++d)
                st_cluster_b64(part_b + off, (rank + d) & (NC - 1), pbv);
        }
        if (tid < 64) {                  // push own 8x32 slice: 8 rows x 8 cg
            int rr = tid >> 3, cgi = tid & 7;
            int fo = rr * HH + c0 + 4 * cgi;
            float4 v = *(const float4*)(inbox + fo);
            uint32_t off = (uint32_t)(fo * 4);
#pragma unroll
            for (int d = 1; d < NC; ++d)
                st_cluster_v4(inbox_b + off, (rank + d) & (NC - 1), v);
        }
        CL_ARRIVE();                     // E0(t)

        // ---- G1a: h1n(t-1)·Wh1  (overlaps E0 exchange) ----
#pragma unroll
        for (int q = 0; q < 4; ++q) acc[q] = 0ull;
        gpart<64>(wp_h1, hx_h1, acc);

        CL_WAIT();                       // E0(t): inbox[0], part[0] valid
        if (tid < 128) {                 // LN stats for h0n(t)
            int r = tid >> 4, s16 = tid & 15;
            float2 pv = part[s16 * RG + r];
#pragma unroll
            for (int o = 8; o; o >>= 1) {
                pv.x += __shfl_xor_sync(0xffffffffu, pv.x, o);
                pv.y += __shfl_xor_sync(0xffffffffu, pv.y, o);
            }
            if (s16 == 0) {
                float mu = pv.x * (1.f / HH);
                float var = pv.y * (1.f / HH) - mu * mu;
                smu[r] = mu; srs[r] = rsqrtf(var + EPSF);
            }
        }
        __syncthreads();
        {                                // rebuild h0n(t): 2 cols/thread
#pragma unroll
            for (int cc = 0; cc < 2; ++cc) {
                int c = tid + cc * 256;
                float gk = sg0[c], bk = sb0[c];
                const float* ib = inbox + c;
                float* hd = h0x + (64 + c) * HP;
#pragma unroll
                for (int r = 0; r < RG; ++r)
                    hd[r] = (ib[r * HH] - smu[r]) * srs[r] * gk + bk;
            }
        }
        __syncthreads();

        // ---- G1b: h0n(t)·Wi1 ----
        gpart<64>(wp_i1, hx_h0, acc);
        if (t + 1 < TSTEPS) {
            xregA = xbaseA[(size_t)(t + 1) * DIN];
            xregB = xbaseB[(size_t)(t + 1) * DIN];
        }
        {
            float* rw = red + p * 320 + lane * 10;
#pragma unroll
            for (int q = 0; q < 4; ++q) *(ull*)(rw + 2 * q) = acc[q];
        }
        __syncthreads();

        // ---- epilogue 1 ----
        {
            float z = 0.f;
#pragma unroll
            for (int i = 0; i < NW; ++i) z += rrd[i * 320];
            z += cb1[ecol];
            float cv = tanhf(z) + h1x[(c0 + ecol) * HP + erow];
            inbox[RG * HH + erow * HH + c0 + ecol] = cv;
            float s = cv, q = cv * cv;
#pragma unroll
            for (int o = 16; o; o >>= 1) {
                s += __shfl_xor_sync(0xffffffffu, s, o);
                q += __shfl_xor_sync(0xffffffffu, q, o);
            }
            if (lane == 0) sp[p] = make_float2(s, q);
        }
        __syncthreads();
        if (tid < RG) {
            float2 pv = sp[tid];
            part[(NC + rank) * RG + tid] = pv;
            uint32_t off = (uint32_t)(((NC + rank) * RG + tid) * 8);
            ull pbv = *(ull*)&pv;
#pragma unroll
            for (int d = 1; d < NC; ++d)
                st_cluster_b64(part_b + off, (rank + d) & (NC - 1), pbv);
        }
        if (tid < 64) {
            int rr = tid >> 3, cgi = tid & 7;
            int fo = RG * HH + rr * HH + c0 + 4 * cgi;
            float4 v = *(const float4*)(inbox + fo);
            uint32_t off = (uint32_t)(fo * 4);
#pragma unroll
            for (int d = 1; d < NC; ++d)
                st_cluster_v4(inbox_b + off, (rank + d) & (NC - 1), v);
        }
        CL_ARRIVE();                     // E1(t)
    }

    // ---- final: wait E1(T-1), rebuild h1n, output head ----
    CL_WAIT();
    if (tid < 128) {
        int r = tid >> 4, s16 = tid & 15;
        float2 pv = part[(NC + s16) * RG + r];
#pragma unroll
        for (int o = 8; o; o >>= 1) {
            pv.x += __shfl_xor_sync(0xffffffffu, pv.x, o);
            pv.y += __shfl_xor_sync(0xffffffffu, pv.y, o);
        }
        if (s16 == 0) {
            float mu = pv.x * (1.f / HH);
            float var = pv.y * (1.f / HH) - mu * mu;
            smu[r] = mu; srs[r] = rsqrtf(var + EPSF);
        }
    }
    __syncthreads();
    {
#pragma unroll
        for (int cc = 0; cc < 2; ++cc) {
            int c = tid + cc * 256;
            float gk = sg1[c], bk = sb1[c];
            const float* ib = inbox + RG * HH + c;
            float* hd = h1x + c * HP;
#pragma unroll
            for (int r = 0; r < RG; ++r)
                hd[r] = (ib[r * HH] - smu[r]) * srs[r] * gk + bk;
        }
    }
    __syncthreads();
    if (rank == 0) {
        float v = 0.f;
#pragma unroll
        for (int m = 0; m < 16; ++m) {
            int k = lane + 32 * m;
            v += h1x[k * HP + p] * Wfc[k];
        }
#pragma unroll
        for (int o = 16; o; o >>= 1) v += __shfl_xor_sync(0xffffffffu, v, o);
        if (lane == 0) out[row0 + p] = v + bfc[0];
    }
}

extern "C" void kernel_launch(void* const* d_in, const int* in_sizes, int n_in,
                              void* d_out, int out_size) {
    (void)in_sizes; (void)n_in; (void)out_size;
    const float* x   = (const float*)d_in[0];
    const float* Wi0 = (const float*)d_in[1];
    const float* bi0 = (const float*)d_in[2];
    const float* Wh0 = (const float*)d_in[3];
    const float* bh0 = (const float*)d_in[4];
    const float* g0  = (const float*)d_in[5];
    const float* be0 = (const float*)d_in[6];
    const float* Wi1 = (const float*)d_in[7];
    const float* bi1 = (const float*)d_in[8];
    const float* Wh1 = (const float*)d_in[9];
    const float* bh1 = (const float*)d_in[10];
    const float* g1  = (const float*)d_in[11];
    const float* be1 = (const float*)d_in[12];
    const float* Wfc = (const float*)d_in[13];
    const float* bfc = (const float*)d_in[14];

    static int inited = 0;
    if (!inited) {
        cudaFuncSetAttribute(rnn_rg8_kernel,
                             cudaFuncAttributeMaxDynamicSharedMemorySize, SMEM_BYTES);
        cudaFuncSetAttribute(rnn_rg8_kernel,
                             cudaFuncAttributeNonPortableClusterSizeAllowed, 1);
        inited = 1;
    }
    rnn_rg8_kernel<<<NGRP * NC, NTHR, SMEM_BYTES>>>(
        x, Wi0, bi0, Wh0, bh0, g0, be0,
        Wi1, bi1, Wh1, bh1, g1, be1,
        Wfc, bfc, (float*)d_out);
}

// round 15
// speedup vs baseline: 3.0008x; 3.0008x over previous
#include <cuda_runtime.h>
#include <cstdint>
#include <cstddef>

#define TSTEPS 1024
#define BATCH  128
#define DIN    64
#define HH     512
#define NGRP   32        // row groups (4 rows each)
#define NC     8         // CTAs per cluster (64-col slices)
#define RG     4         // rows per group
#define CW     64        // cols per CTA slice
#define NTHR   256
#define NW     8         // warps = k-phase pairs
#define HP     8         // float pitch per k-row (4 rows + 4 pad, 16B-aligned rows)
#define EPSF   1e-5f

// ---- shared memory layout (float offsets) ----
#define OF_H0X   0                         // [576][HP]: rows 0..63 = x_t, 64..575 = h0n
#define OF_H1X   (OF_H0X + 576 * HP)       // [512][HP]
#define OF_RED   (OF_H1X + 512 * HP)       // [8][16][20]
#define OF_INBOX (OF_RED + 8 * 16 * 20)    // [2][RG][HH]
#define OF_PART  (OF_INBOX + 2 * RG * HH)  // [2][NC][RG] float2
#define OF_SG0   (OF_PART + 2 * NC * RG * 2)
#define OF_SB0   (OF_SG0 + HH)
#define OF_SG1   (OF_SB0 + HH)
#define OF_SB1   (OF_SG1 + HH)
#define OF_CB0   (OF_SB1 + HH)
#define OF_CB1   (OF_CB0 + CW)
#define OF_SP    (OF_CB1 + CW)             // [8] float2 (per-warp LN partials)
#define OF_SMU   (OF_SP + 16)
#define OF_SRS   (OF_SMU + RG)
#define SMEM_FL  (OF_SRS + RG)
#define SMEM_BYTES (SMEM_FL * 4)

typedef unsigned long long ull;

__device__ __forceinline__ ull ffma2(ull a, ull b, ull c) {
    ull d;
    asm("fma.rn.f32x2 %0, %1, %2, %3;" : "=l"(d) : "l"(a), "l"(b), "l"(c));
    return d;
}
__device__ __forceinline__ ull dup2(float f) {
    ull d;
    asm("mov.b64 %0, {%1, %1};" : "=l"(d) : "f"(f));
    return d;
}
__device__ __forceinline__ uint32_t smem_u32(const void* p) {
    uint32_t a;
    asm("{ .reg .u64 t; cvta.to.shared.u64 t, %1; cvt.u32.u64 %0, t; }" : "=r"(a) : "l"(p));
    return a;
}
__device__ __forceinline__ void st_cluster_v4(uint32_t laddr, int rank, float4 v) {
    uint32_t ra;
    asm volatile("mapa.shared::cluster.u32 %0, %1, %2;" : "=r"(ra) : "r"(laddr), "r"(rank));
    asm volatile("st.shared::cluster.v4.b32 [%0], {%1,%2,%3,%4};"
                 :: "r"(ra), "r"(__float_as_uint(v.x)), "r"(__float_as_uint(v.y)),
                    "r"(__float_as_uint(v.z)), "r"(__float_as_uint(v.w)) : "memory");
}
__device__ __forceinline__ void st_cluster_b64(uint32_t laddr, int rank, ull v) {
    uint32_t ra;
    asm volatile("mapa.shared::cluster.u32 %0, %1, %2;" : "=r"(ra) : "r"(laddr), "r"(rank));
    asm volatile("st.shared::cluster.b64 [%0], %1;" :: "r"(ra), "l"(v) : "memory");
}
__device__ __forceinline__ uint32_t ctarank() {
    uint32_t r;
    asm("mov.u32 %0, %%cluster_ctarank;" : "=r"(r));
    return r;
}
#define CL_ARRIVE() asm volatile("barrier.cluster.arrive.aligned;" ::: "memory")
#define CL_WAIT()   asm volatile("barrier.cluster.wait.aligned;" ::: "memory")

// GEMV slice: warp covers 2 k-rows per iter (half-warps), 4 cols x 4 rows/thread.
// k = i*16 + 2p + khalf. One LDG.128 + one broadcast LDS.128 feeds 8 FFMA2.
template<int ITERS>
__device__ __forceinline__ void gpart(const float* __restrict__ Wp,
                                      const float* __restrict__ hp, ull* acc) {
#pragma unroll 8
    for (int i = 0; i < ITERS; ++i) {
        ulonglong2 w = *(const ulonglong2*)(Wp + (size_t)i * 16 * HH);
        float4 hv = *(const float4*)(hp + i * 16 * HP);
        ull d0 = dup2(hv.x), d1 = dup2(hv.y), d2 = dup2(hv.z), d3 = dup2(hv.w);
        acc[0] = ffma2(d0, w.x, acc[0]); acc[1] = ffma2(d0, w.y, acc[1]);
        acc[2] = ffma2(d1, w.x, acc[2]); acc[3] = ffma2(d1, w.y, acc[3]);
        acc[4] = ffma2(d2, w.x, acc[4]); acc[5] = ffma2(d2, w.y, acc[5]);
        acc[6] = ffma2(d3, w.x, acc[6]); acc[7] = ffma2(d3, w.y, acc[7]);
    }
}

// Combine khalf partial sums across half-warps, then dump lanes 0..15 to red.
__device__ __forceinline__ void dump_acc(ull* acc, float* red, int p, int lane) {
    const ull one2 = dup2(1.0f);
#pragma unroll
    for (int q = 0; q < 8; ++q) {
        ull v = __shfl_xor_sync(0xffffffffu, acc[q], 16);
        acc[q] = ffma2(v, one2, acc[q]);          // packed pairwise add
    }
    if (lane < 16) {
        float* rw = red + p * 320 + lane * 20;
#pragma unroll
        for (int q = 0; q < 4; ++q) {
            ulonglong2 tv; tv.x = acc[2 * q]; tv.y = acc[2 * q + 1];
            *(ulonglong2*)(rw + 4 * q) = tv;
        }
    }
}

__global__ void __launch_bounds__(NTHR, 2) __cluster_dims__(NC, 1, 1)
rnn_k2_kernel(
    const float* __restrict__ x,
    const float* __restrict__ Wi0, const float* __restrict__ bi0,
    const float* __restrict__ Wh0, const float* __restrict__ bh0,
    const float* __restrict__ g0,  const float* __restrict__ be0,
    const float* __restrict__ Wi1, const float* __restrict__ bi1,
    const float* __restrict__ Wh1, const float* __restrict__ bh1,
    const float* __restrict__ g1,  const float* __restrict__ be1,
    const float* __restrict__ Wfc, const float* __restrict__ bfc,
    float* __restrict__ out)
{
    extern __shared__ float sm[];
    float*  h0x   = sm + OF_H0X;
    float*  h1x   = sm + OF_H1X;
    float*  red   = sm + OF_RED;
    float*  inbox = sm + OF_INBOX;
    float2* part  = (float2*)(sm + OF_PART);
    float*  sg0   = sm + OF_SG0;  float* sb0 = sm + OF_SB0;
    float*  sg1   = sm + OF_SG1;  float* sb1 = sm + OF_SB1;
    float*  cb0   = sm + OF_CB0;  float* cb1 = sm + OF_CB1;
    float2* sp    = (float2*)(sm + OF_SP);
    float*  smu   = sm + OF_SMU;  float* srs = sm + OF_SRS;

    const int tid   = threadIdx.x;
    const int lane  = tid & 31;
    const int p     = tid >> 5;          // warp id (k-phase pair)
    const int cgo   = (lane & 15) * 4;   // col offset (16 groups x 4 cols = 64)
    const int khalf = lane >> 4;         // which of the 2 k-rows this half-warp does
    const int rank  = (int)ctarank();
    const int g     = blockIdx.x >> 3;
    const int c0    = rank * CW;
    const int row0  = g * RG;
    const int kof   = 2 * p + khalf;     // k residue mod 16

    const uint32_t inbox_b = smem_u32(inbox);
    const uint32_t part_b  = smem_u32(part);

    // epilogue constants: 1 output/thread; warp p covers row p>>1, half p&1
    const int erow = tid >> 6;          // 0..3
    const int ecol = tid & 63;          // 0..63
    const float* rrd = red + (ecol >> 2) * 20
                           + (erow * 2 + ((ecol & 3) >> 1)) * 2 + (ecol & 1);

    // per-thread GEMV base pointers
    const float* wp_i0 = Wi0 + c0 + (size_t)kof * HH + cgo;
    const float* wp_h0 = Wh0 + c0 + (size_t)kof * HH + cgo;
    const float* wp_i1 = Wi1 + c0 + (size_t)kof * HH + cgo;
    const float* wp_h1 = Wh1 + c0 + (size_t)kof * HH + cgo;
    const float* hx_x  = h0x + kof * HP;
    const float* hx_h0 = h0x + (64 + kof) * HP;
    const float* hx_h1 = h1x + kof * HP;

    // ---- init ----
    sg0[tid] = g0[tid];             sb0[tid] = be0[tid];
    sg0[tid + 256] = g0[tid + 256]; sb0[tid + 256] = be0[tid + 256];
    sg1[tid] = g1[tid];             sb1[tid] = be1[tid];
    sg1[tid + 256] = g1[tid + 256]; sb1[tid + 256] = be1[tid + 256];
    if (tid < CW) {
        cb0[tid] = bi0[c0 + tid] + bh0[c0 + tid];
        cb1[tid] = bi1[c0 + tid] + bh1[c0 + tid];
    }
    for (int i = tid; i < 576 * HP; i += NTHR) h0x[i] = 0.f;
    for (int i = tid; i < 512 * HP; i += NTHR) h1x[i] = 0.f;
    __syncthreads();
    CL_ARRIVE();     // publishes init; pairs with first E1 wait

    // x staging: 4 rows x 64 k = 256 threads exactly
    const int xr = tid >> 6, xk = tid & 63;
    const float* xbase = x + (size_t)(row0 + xr) * TSTEPS * DIN + xk;
    float xreg = xbase[0];

    ull acc[8];

    for (int t = 0; t < TSTEPS; ++t) {
        h0x[xk * HP + xr] = xreg;
        __syncthreads();

        // ---- G0: x·Wi0 + h0n(t-1)·Wh0  (overlaps E1(t-1) exchange) ----
#pragma unroll
        for (int q = 0; q < 8; ++q) acc[q] = 0ull;
        gpart<4>(wp_i0, hx_x, acc);
        gpart<32>(wp_h0, hx_h0, acc);

        CL_WAIT();                       // E1(t-1): inbox[1], part[1] valid
        if (t > 0 && tid < 32) {         // LN stats for h1n(t-1)
            int r = tid >> 3, s8 = tid & 7;
            float2 pv = part[(NC + s8) * RG + r];
#pragma unroll
            for (int o = 4; o; o >>= 1) {
                pv.x += __shfl_xor_sync(0xffffffffu, pv.x, o);
                pv.y += __shfl_xor_sync(0xffffffffu, pv.y, o);
            }
            if (s8 == 0) {
                float mu = pv.x * (1.f / HH);
                float var = pv.y * (1.f / HH) - mu * mu;
                smu[r] = mu; srs[r] = rsqrtf(var + EPSF);
            }
        }
        __syncthreads();
        if (t > 0) {                     // rebuild h1n(t-1): 2 cols/thread
#pragma unroll
            for (int cc = 0; cc < 2; ++cc) {
                int c = tid + cc * 256;
                float gk = sg1[c], bk = sb1[c];
                const float* ib = inbox + RG * HH + c;
                float4 u;
                u.x = (ib[0 * HH] - smu[0]) * srs[0] * gk + bk;
                u.y = (ib[1 * HH] - smu[1]) * srs[1] * gk + bk;
                u.z = (ib[2 * HH] - smu[2]) * srs[2] * gk + bk;
                u.w = (ib[3 * HH] - smu[3]) * srs[3] * gk + bk;
                *(float4*)(h1x + c * HP) = u;
            }
        }
        dump_acc(acc, red, p, lane);
        __syncthreads();

        // ---- epilogue 0 ----
        {
            float z = 0.f;
#pragma unroll
            for (int i = 0; i < NW; ++i) z += rrd[i * 320];
            z += cb0[ecol];
            float cv = tanhf(z) + h0x[(64 + c0 + ecol) * HP + erow];
            inbox[erow * HH + c0 + ecol] = cv;
            float s = cv, q = cv * cv;
#pragma unroll
            for (int o = 16; o; o >>= 1) {
                s += __shfl_xor_sync(0xffffffffu, s, o);
                q += __shfl_xor_sync(0xffffffffu, q, o);
            }
            if (lane == 0) sp[p] = make_float2(s, q);   // warp p: row p>>1, half p&1
        }
        __syncthreads();
        if (tid < RG) {
            float2 a = sp[2 * tid], b = sp[2 * tid + 1];
            float2 pv = make_float2(a.x + b.x, a.y + b.y);
            part[rank * RG + tid] = pv;
            uint32_t off = (uint32_t)((rank * RG + tid) * 8);
            ull pbv = *(ull*)&pv;
#pragma unroll
            for (int d = 1; d < NC; ++d)
                st_cluster_b64(part_b + off, (rank + d) & (NC - 1), pbv);
        }
        if (tid < 64) {                  // push own 4x64 slice: 4 rows x 16 cg
            int rr = tid >> 4, cgi = tid & 15;
            int fo = rr * HH + c0 + 4 * cgi;
            float4 v = *(const float4*)(inbox + fo);
            uint32_t off = (uint32_t)(fo * 4);
#pragma unroll
            for (int d = 1; d < NC; ++d)
                st_cluster_v4(inbox_b + off, (rank + d) & (NC - 1), v);
        }
        CL_ARRIVE();                     // E0(t)

        // ---- G1a: h1n(t-1)·Wh1  (overlaps E0 exchange) ----
#pragma unroll
        for (int q = 0; q < 8; ++q) acc[q] = 0ull;
        gpart<32>(wp_h1, hx_h1, acc);

        CL_WAIT();                       // E0(t): inbox[0], part[0] valid
        if (tid < 32) {                  // LN stats for h0n(t)
            int r = tid >> 3, s8 = tid & 7;
            float2 pv = part[s8 * RG + r];
#pragma unroll
            for (int o = 4; o; o >>= 1) {
                pv.x += __shfl_xor_sync(0xffffffffu, pv.x, o);
                pv.y += __shfl_xor_sync(0xffffffffu, pv.y, o);
            }
            if (s8 == 0) {
                float mu = pv.x * (1.f / HH);
                float var = pv.y * (1.f / HH) - mu * mu;
                smu[r] = mu; srs[r] = rsqrtf(var + EPSF);
            }
        }
        __syncthreads();
        {                                // rebuild h0n(t): 2 cols/thread
#pragma unroll
            for (int cc = 0; cc < 2; ++cc) {
                int c = tid + cc * 256;
                float gk = sg0[c], bk = sb0[c];
                const float* ib = inbox + c;
                float4 u;
                u.x = (ib[0 * HH] - smu[0]) * srs[0] * gk + bk;
                u.y = (ib[1 * HH] - smu[1]) * srs[1] * gk + bk;
                u.z = (ib[2 * HH] - smu[2]) * srs[2] * gk + bk;
                u.w = (ib[3 * HH] - smu[3]) * srs[3] * gk + bk;
                *(float4*)(h0x + (64 + c) * HP) = u;
            }
        }
        __syncthreads();

        // ---- G1b: h0n(t)·Wi1 ----
        gpart<32>(wp_i1, hx_h0, acc);
        if (t + 1 < TSTEPS) xreg = xbase[(size_t)(t + 1) * DIN];
        dump_acc(acc, red, p, lane);
        __syncthreads();

        // ---- epilogue 1 ----
        {
            float z = 0.f;
#pragma unroll
            for (int i = 0; i < NW; ++i) z += rrd[i * 320];
            z += cb1[ecol];
            float cv = tanhf(z) + h1x[(c0 + ecol) * HP + erow];
            inbox[RG * HH + erow * HH + c0 + ecol] = cv;
            float s = cv, q = cv * cv;
#pragma unroll
            for (int o = 16; o; o >>= 1) {
                s += __shfl_xor_sync(0xffffffffu, s, o);
                q += __shfl_xor_sync(0xffffffffu, q, o);
            }
            if (lane == 0) sp[p] = make_float2(s, q);
        }
        __syncthreads();
        if (tid < RG) {
            float2 a = sp[2 * tid], b = sp[2 * tid + 1];
            float2 pv = make_float2(a.x + b.x, a.y + b.y);
            part[(NC + rank) * RG + tid] = pv;
            uint32_t off = (uint32_t)(((NC + rank) * RG + tid) * 8);
            ull pbv = *(ull*)&pv;
#pragma unroll
            for (int d = 1; d < NC; ++d)
                st_cluster_b64(part_b + off, (rank + d) & (NC - 1), pbv);
        }
        if (tid < 64) {
            int rr = tid >> 4, cgi = tid & 15;
            int fo = RG * HH + rr * HH + c0 + 4 * cgi;
            float4 v = *(const float4*)(inbox + fo);
            uint32_t off = (uint32_t)(fo * 4);
#pragma unroll
            for (int d = 1; d < NC; ++d)
                st_cluster_v4(inbox_b + off, (rank + d) & (NC - 1), v);
        }
        CL_ARRIVE();                     // E1(t)
    }

    // ---- final: wait E1(T-1), rebuild h1n, output head ----
    CL_WAIT();
    if (tid < 32) {
        int r = tid >> 3, s8 = tid & 7;
        float2 pv = part[(NC + s8) * RG + r];
#pragma unroll
        for (int o = 4; o; o >>= 1) {
            pv.x += __shfl_xor_sync(0xffffffffu, pv.x, o);
            pv.y += __shfl_xor_sync(0xffffffffu, pv.y, o);
        }
        if (s8 == 0) {
            float mu = pv.x * (1.f / HH);
            float var = pv.y * (1.f / HH) - mu * mu;
            smu[r] = mu; srs[r] = rsqrtf(var + EPSF);
        }
    }
    __syncthreads();
    {
#pragma unroll
        for (int cc = 0; cc < 2; ++cc) {
            int c = tid + cc * 256;
            float gk = sg1[c], bk = sb1[c];
            const float* ib = inbox + RG * HH + c;
            float* hd = h1x + c * HP;
#pragma unroll
            for (int r = 0; r < RG; ++r)
                hd[r] = (ib[r * HH] - smu[r]) * srs[r] * gk + bk;
        }
    }
    __syncthreads();
    if (rank == 0 && p < RG) {
        float v = 0.f;
#pragma unroll
        for (int m = 0; m < 16; ++m) {
            int k = lane + 32 * m;
            v += h1x[k * HP + p] * Wfc[k];
        }
#pragma unroll
        for (int o = 16; o; o >>= 1) v += __shfl_xor_sync(0xffffffffu, v, o);
        if (lane == 0) out[row0 + p] = v + bfc[0];
    }
}

extern "C" void kernel_launch(void* const* d_in, const int* in_sizes, int n_in,
                              void* d_out, int out_size) {
    (void)in_sizes; (void)n_in; (void)out_size;
    const float* x   = (const float*)d_in[0];
    const float* Wi0 = (const float*)d_in[1];
    const float* bi0 = (const float*)d_in[2];
    const float* Wh0 = (const float*)d_in[3];
    const float* bh0 = (const float*)d_in[4];
    const float* g0  = (const float*)d_in[5];
    const float* be0 = (const float*)d_in[6];
    const float* Wi1 = (const float*)d_in[7];
    const float* bi1 = (const float*)d_in[8];
    const float* Wh1 = (const float*)d_in[9];
    const float* bh1 = (const float*)d_in[10];
    const float* g1  = (const float*)d_in[11];
    const float* be1 = (const float*)d_in[12];
    const float* Wfc = (const float*)d_in[13];
    const float* bfc = (const float*)d_in[14];

    static int inited = 0;
    if (!inited) {
        cudaFuncSetAttribute(rnn_k2_kernel,
                             cudaFuncAttributeMaxDynamicSharedMemorySize, SMEM_BYTES);
        inited = 1;
    }
    rnn_k2_kernel<<<NGRP * NC, NTHR, SMEM_BYTES>>>(
        x, Wi0, bi0, Wh0, bh0, g0, be0,
        Wi1, bi1, Wh1, bh1, g1, be1,
        Wfc, bfc, (float*)d_out);
}